// round 11
// baseline (speedup 1.0000x reference)
#include <cuda_runtime.h>

#define NB    4096   // batch
#define DIMC  101    // class dim
#define GCLS  100    // classes used by softmax
#define RR    56     // rows
#define LL    4      // lanes
#define RL    224    // RR*LL floats per (n,c) plane
#define SPB   8      // samples per block
#define NBLK  (NB / SPB)      // 512 blocks -> single wave at 4 blocks/SM
#define THREADS 448           // SPB * RR = 14 warps -> 56 warps/SM resident
#define CHUNK 5               // front-batched LDG.128 per iteration

// Scratch (allocation-free rule: __device__ globals; zero-init at load)
__device__ float        g_lossk[NB];
__device__ unsigned int g_done;     // last-block ticket; reset every run

__global__ void __launch_bounds__(THREADS, 4) pos_loss_kernel(
    const float* __restrict__ x,
    const int*   __restrict__ labels,   // JAX default: int64 w/o x64 flag == int32
    float*       __restrict__ out)
{
    __shared__ float         s_pos[SPB][RR][LL];
    __shared__ unsigned char s_valid[SPB][RR][LL];
    __shared__ float         s_ll[SPB][LL];
    __shared__ bool          s_amLast;

    const int t     = threadIdx.x;
    const int n_sub = t / RR;           // 0..7
    const int r     = t - n_sub * RR;   // 0..55
    const int n     = blockIdx.x * SPB + n_sub;

    // labels[n, r, 0..3] as int4 (16B aligned) — early, independent of x stream
    int4 lab = ((const int4*)labels)[(size_t)n * RR + r];
    s_valid[n_sub][r][0] = (lab.x < GCLS);
    s_valid[n_sub][r][1] = (lab.y < GCLS);
    s_valid[n_sub][r][2] = (lab.z < GCLS);
    s_valid[n_sub][r][3] = (lab.w < GCLS);

    // ---------- Phase 1: softmax expected position, 4 lanes per thread ----------
    // x[n, c, r, 0..3] -> float4 at (n*DIMC + c)*56 + r ; class stride = 56 float4
    const float4* xb = (const float4*)(x + (size_t)n * (DIMC * RL)) + r;

    float s0 = 0.f, s1 = 0.f, s2 = 0.f, s3 = 0.f;
    float w0 = 0.f, w1 = 0.f, w2 = 0.f, w3 = 0.f;

    // unroll 2 -> 10-class static window (proven minimum of the search;
    // unroll 4 spills at the 32-reg allocation).
    #pragma unroll 2
    for (int cb = 0; cb < GCLS; cb += CHUNK) {
        // Batch CHUNK LDG.128 up front; streaming (evict-first) hint.
        float4 v[CHUNK];
        #pragma unroll
        for (int j = 0; j < CHUNK; ++j)
            v[j] = __ldcs(&xb[(size_t)(cb + j) * (RL / 4)]);

        #pragma unroll
        for (int j = 0; j < CHUNK; ++j) {
            float fc = (float)(cb + j);
            float e0 = __expf(v[j].x);
            float e1 = __expf(v[j].y);
            float e2 = __expf(v[j].z);
            float e3 = __expf(v[j].w);
            s0 += e0; w0 = fmaf(e0, fc, w0);
            s1 += e1; w1 = fmaf(e1, fc, w1);
            s2 += e2; w2 = fmaf(e2, fc, w2);
            s3 += e3; w3 = fmaf(e3, fc, w3);
        }
    }
    s_pos[n_sub][r][0] = w0 / s0;
    s_pos[n_sub][r][1] = w1 / s1;
    s_pos[n_sub][r][2] = w2 / s2;
    s_pos[n_sub][r][3] = w3 / s3;

    __syncthreads();

    // ---------- Phase 2: per-(sample,lane) bounds + second-difference loss ----------
    if (t < SPB * LL) {            // 32 tasks: one warp
        const int ns = t / LL;
        const int l  = t - ns * LL;

        bool v0 = s_valid[ns][0][l] != 0;
        bool v1 = s_valid[ns][1][l] != 0;
        bool vl = s_valid[ns][RR - 1][l] != 0;

        int first_up = -1, first_dn = -1;
        bool prev = v0;
        #pragma unroll
        for (int rr = 0; rr < RR - 1; ++rr) {
            bool cur = s_valid[ns][rr + 1][l] != 0;
            if (first_up < 0 && !prev && cur) first_up = rr + 1;
            if (first_dn < 0 && prev && !cur) first_dn = rr;
            prev = cur;
        }

        bool top_exists = v0 || (first_up >= 0);
        int  top        = v0 ? 0 : (first_up >= 0 ? first_up : 0);

        bool cond0       = v0 && !v1;
        bool down_exists = cond0 || vl || (first_dn >= 0);
        int  down        = cond0 ? 0 : (vl ? (RR - 1) : (first_dn >= 0 ? first_dn : 0));

        if (!(top_exists && down_exists)) { top = 0; down = 0; }

        int count = down - top - 1;

        float lane_sum = 0.f;
        for (int i = top; i <= down - 2; ++i) {
            float p0 = s_pos[ns][i    ][l];
            float p1 = s_pos[ns][i + 1][l];
            float p2 = s_pos[ns][i + 2][l];
            lane_sum += fabsf((p0 - p1) - (p1 - p2));
        }

        s_ll[ns][l] = (count >= 1) ? (lane_sum / (float)count) : 0.f;
    }
    __syncthreads();

    if (t < SPB) {
        float lk = (((s_ll[t][0] + s_ll[t][1]) + s_ll[t][2]) + s_ll[t][3]) * 0.125f;
        g_lossk[blockIdx.x * SPB + t] = lk;
    }

    // ---------- Fused deterministic final reduction (last block wins) ----------
    __threadfence();
    if (t == 0) {
        unsigned int v = atomicAdd(&g_done, 1u);
        s_amLast = (v == gridDim.x - 1);
    }
    __syncthreads();

    if (s_amLast) {
        __threadfence();
        __shared__ float ssum[128];
        __shared__ int   scnt[128];
        if (t < 128) {
            float s = 0.f; int c = 0;
            #pragma unroll 8
            for (int i = t; i < NB; i += 128) {
                float v = g_lossk[i];
                s += v;
                c += (v != 0.f) ? 1 : 0;
            }
            ssum[t] = s; scnt[t] = c;
        }
        __syncthreads();
        #pragma unroll
        for (int st = 64; st > 0; st >>= 1) {
            if (t < st) { ssum[t] += ssum[t + st]; scnt[t] += scnt[t + st]; }
            __syncthreads();
        }
        if (t == 0) {
            out[0] = (scnt[0] > 0) ? (ssum[0] / (float)scnt[0]) : 0.f;
            g_done = 0;   // reset ticket for next graph replay
        }
    }
}

extern "C" void kernel_launch(void* const* d_in, const int* in_sizes, int n_in,
                              void* d_out, int out_size)
{
    const float* x      = (const float*)d_in[0];
    const int*   labels = (const int*)d_in[1];
    float*       out    = (float*)d_out;

    pos_loss_kernel<<<NBLK, THREADS>>>(x, labels, out);
}

// round 12
// speedup vs baseline: 1.0395x; 1.0395x over previous
#include <cuda_runtime.h>

#define NB    4096   // batch
#define DIMC  101    // class dim
#define GCLS  100    // classes used by softmax
#define RR    56     // rows
#define LL    4      // lanes
#define RL    224    // RR*LL floats per (n,c) plane
#define SPB   4      // samples per block (proven best shape)
#define NBLK  (NB / SPB)      // 1024 blocks -> single wave at 7 blocks/SM
#define THREADS 224           // SPB * RR
#define CHUNK 4               // front-batched LDG.128 per iteration (100 = 25*4 exact)

// Scratch (allocation-free rule: __device__ globals; zero-init at load)
__device__ float        g_lossk[NB];
__device__ unsigned int g_done;     // last-block ticket; reset every run

__global__ void __launch_bounds__(THREADS, 7) pos_loss_kernel(
    const float* __restrict__ x,
    const int*   __restrict__ labels,   // JAX default: int64 w/o x64 flag == int32
    float*       __restrict__ out)
{
    __shared__ float         s_pos[SPB][RR][LL];
    __shared__ unsigned char s_valid[SPB][RR][LL];
    __shared__ float         s_ll[SPB][LL];
    __shared__ bool          s_amLast;

    const int t     = threadIdx.x;
    const int n_sub = t / RR;           // 0..3
    const int r     = t - n_sub * RR;   // 0..55
    const int n     = blockIdx.x * SPB + n_sub;

    // labels[n, r, 0..3] as int4 (16B aligned) — early, independent of x stream
    int4 lab = ((const int4*)labels)[(size_t)n * RR + r];
    s_valid[n_sub][r][0] = (lab.x < GCLS);
    s_valid[n_sub][r][1] = (lab.y < GCLS);
    s_valid[n_sub][r][2] = (lab.z < GCLS);
    s_valid[n_sub][r][3] = (lab.w < GCLS);

    // ---------- Phase 1: softmax expected position, 4 lanes per thread ----------
    // x[n, c, r, 0..3] -> float4 at (n*DIMC + c)*56 + r ; class stride = 56 float4
    const float4* xb = (const float4*)(x + (size_t)n * (DIMC * RL)) + r;

    float s0 = 0.f, s1 = 0.f, s2 = 0.f, s3 = 0.f;
    float w0 = 0.f, w1 = 0.f, w2 = 0.f, w3 = 0.f;

    // unroll 2 -> 8-class static window: ptxas hoists next chunk's LDGs above
    // the current MUFU tail, well inside the 32-reg allocation (no spill).
    #pragma unroll 2
    for (int cb = 0; cb < GCLS; cb += CHUNK) {
        // Batch CHUNK LDG.128 up front; streaming (evict-first) hint.
        float4 v[CHUNK];
        #pragma unroll
        for (int j = 0; j < CHUNK; ++j)
            v[j] = __ldcs(&xb[(size_t)(cb + j) * (RL / 4)]);

        #pragma unroll
        for (int j = 0; j < CHUNK; ++j) {
            float fc = (float)(cb + j);
            float e0 = __expf(v[j].x);
            float e1 = __expf(v[j].y);
            float e2 = __expf(v[j].z);
            float e3 = __expf(v[j].w);
            s0 += e0; w0 = fmaf(e0, fc, w0);
            s1 += e1; w1 = fmaf(e1, fc, w1);
            s2 += e2; w2 = fmaf(e2, fc, w2);
            s3 += e3; w3 = fmaf(e3, fc, w3);
        }
    }
    s_pos[n_sub][r][0] = w0 / s0;
    s_pos[n_sub][r][1] = w1 / s1;
    s_pos[n_sub][r][2] = w2 / s2;
    s_pos[n_sub][r][3] = w3 / s3;

    __syncthreads();

    // ---------- Phase 2: per-(sample,lane) bounds + second-difference loss ----------
    if (t < SPB * LL) {
        const int ns = t / LL;
        const int l  = t - ns * LL;

        bool v0 = s_valid[ns][0][l] != 0;
        bool v1 = s_valid[ns][1][l] != 0;
        bool vl = s_valid[ns][RR - 1][l] != 0;

        int first_up = -1, first_dn = -1;
        bool prev = v0;
        #pragma unroll
        for (int rr = 0; rr < RR - 1; ++rr) {
            bool cur = s_valid[ns][rr + 1][l] != 0;
            if (first_up < 0 && !prev && cur) first_up = rr + 1;
            if (first_dn < 0 && prev && !cur) first_dn = rr;
            prev = cur;
        }

        bool top_exists = v0 || (first_up >= 0);
        int  top        = v0 ? 0 : (first_up >= 0 ? first_up : 0);

        bool cond0       = v0 && !v1;
        bool down_exists = cond0 || vl || (first_dn >= 0);
        int  down        = cond0 ? 0 : (vl ? (RR - 1) : (first_dn >= 0 ? first_dn : 0));

        if (!(top_exists && down_exists)) { top = 0; down = 0; }

        int count = down - top - 1;

        float lane_sum = 0.f;
        for (int i = top; i <= down - 2; ++i) {
            float p0 = s_pos[ns][i    ][l];
            float p1 = s_pos[ns][i + 1][l];
            float p2 = s_pos[ns][i + 2][l];
            lane_sum += fabsf((p0 - p1) - (p1 - p2));
        }

        s_ll[ns][l] = (count >= 1) ? (lane_sum / (float)count) : 0.f;
    }
    __syncthreads();

    if (t < SPB) {
        float lk = (((s_ll[t][0] + s_ll[t][1]) + s_ll[t][2]) + s_ll[t][3]) * 0.125f;
        g_lossk[blockIdx.x * SPB + t] = lk;
    }

    // ---------- Fused deterministic final reduction (last block wins) ----------
    __threadfence();
    if (t == 0) {
        unsigned int v = atomicAdd(&g_done, 1u);
        s_amLast = (v == gridDim.x - 1);
    }
    __syncthreads();

    if (s_amLast) {
        __threadfence();
        __shared__ float ssum[128];
        __shared__ int   scnt[128];
        if (t < 128) {
            float s = 0.f; int c = 0;
            #pragma unroll 8
            for (int i = t; i < NB; i += 128) {
                float v = g_lossk[i];
                s += v;
                c += (v != 0.f) ? 1 : 0;
            }
            ssum[t] = s; scnt[t] = c;
        }
        __syncthreads();
        #pragma unroll
        for (int st = 64; st > 0; st >>= 1) {
            if (t < st) { ssum[t] += ssum[t + st]; scnt[t] += scnt[t + st]; }
            __syncthreads();
        }
        if (t == 0) {
            out[0] = (scnt[0] > 0) ? (ssum[0] / (float)scnt[0]) : 0.f;
            g_done = 0;   // reset ticket for next graph replay
        }
    }
}

extern "C" void kernel_launch(void* const* d_in, const int* in_sizes, int n_in,
                              void* d_out, int out_size)
{
    const float* x      = (const float*)d_in[0];
    const int*   labels = (const int*)d_in[1];
    float*       out    = (float*)d_out;

    pos_loss_kernel<<<NBLK, THREADS>>>(x, labels, out);
}